// round 2
// baseline (speedup 1.0000x reference)
#include <cuda_runtime.h>
#include <math.h>

// Problem constants
#define D_MODEL 256
#define B_      4
#define TQ_     9
#define TS_     8
#define HW_     1024
#define NH_     8
#define DH_     32
#define MLP_    1024

static const int MS = B_ * TS_ * HW_;   // 32768 spatial tokens
static const int MT = B_ * TQ_ * HW_;   // 36864 full tokens

// Scratch (device globals — no allocations allowed)
__device__ float g_ln [MT * D_MODEL];
__device__ float g_q  [MT * D_MODEL];
__device__ float g_k  [MT * D_MODEL];
__device__ float g_v  [MT * D_MODEL];
__device__ float g_ao [MT * D_MODEL];
__device__ float g_x  [MT * D_MODEL];
__device__ float g_y  [MT * D_MODEL];
__device__ float g_tmp[MT * D_MODEL];
__device__ float g_hid[MT * MLP_];

// ---------------------------------------------------------------------------
// LayerNorm: one warp per token, 8 elems/lane (D=256)
// Token m maps to source token b*src_tpb + (m % dst_tpb), b = m / dst_tpb.
// ---------------------------------------------------------------------------
__global__ void ln_kernel(const float* __restrict__ src, float* __restrict__ dst,
                          const float* __restrict__ gam, const float* __restrict__ bet,
                          int M, int src_tpb, int dst_tpb)
{
    int warp = (blockIdx.x * blockDim.x + threadIdx.x) >> 5;
    int lane = threadIdx.x & 31;
    if (warp >= M) return;
    int bb = warp / dst_tpb;
    int rem = warp % dst_tpb;
    const float* x = src + ((size_t)bb * src_tpb + rem) * D_MODEL;

    float vals[8];
    float s = 0.f, s2 = 0.f;
#pragma unroll
    for (int j = 0; j < 8; j++) {
        float v = x[lane + 32 * j];
        vals[j] = v; s += v; s2 += v * v;
    }
#pragma unroll
    for (int o = 16; o; o >>= 1) {
        s  += __shfl_xor_sync(0xffffffffu, s,  o);
        s2 += __shfl_xor_sync(0xffffffffu, s2, o);
    }
    float mean = s * (1.f / D_MODEL);
    float var  = s2 * (1.f / D_MODEL) - mean * mean;
    float rstd = rsqrtf(var + 1e-5f);

    float* y = dst + (size_t)warp * D_MODEL;
#pragma unroll
    for (int j = 0; j < 8; j++) {
        int d = lane + 32 * j;
        y[d] = (vals[j] - mean) * rstd * gam[d] + bet[d];
    }
}

// ---------------------------------------------------------------------------
// Tiled fp32 GEMM: C[M,N] = A[M,K] @ W[K,N] + bias (+ optional GELU / residual)
// BM=BN=64, BK=16, 256 threads, 4x4 microtile. M,N,K divisible by tile sizes.
// ---------------------------------------------------------------------------
template <bool GELU, bool RES>
__global__ __launch_bounds__(256)
void gemm_kernel(const float* __restrict__ A, const float* __restrict__ W,
                 const float* __restrict__ bias, const float* __restrict__ res,
                 float* __restrict__ C, int M, int N, int K)
{
    __shared__ float As[16][65];
    __shared__ float Bs[16][64];

    const int tid = threadIdx.x;
    const int m0 = blockIdx.y * 64;
    const int n0 = blockIdx.x * 64;
    const int tx = tid & 15;   // n micro
    const int ty = tid >> 4;   // m micro

    float acc[4][4] = {};

    for (int k0 = 0; k0 < K; k0 += 16) {
        // load A tile 64x16
#pragma unroll
        for (int i = tid; i < 64 * 16; i += 256) {
            int m = i >> 4, k = i & 15;
            As[k][m] = A[(size_t)(m0 + m) * K + k0 + k];
        }
        // load W tile 16x64
#pragma unroll
        for (int i = tid; i < 16 * 64; i += 256) {
            int k = i >> 6, n = i & 63;
            Bs[k][n] = W[(size_t)(k0 + k) * N + n0 + n];
        }
        __syncthreads();
#pragma unroll
        for (int k = 0; k < 16; k++) {
            float ra[4], rb[4];
#pragma unroll
            for (int i = 0; i < 4; i++) ra[i] = As[k][ty * 4 + i];
#pragma unroll
            for (int j = 0; j < 4; j++) rb[j] = Bs[k][tx * 4 + j];
#pragma unroll
            for (int i = 0; i < 4; i++)
#pragma unroll
                for (int j = 0; j < 4; j++)
                    acc[i][j] = fmaf(ra[i], rb[j], acc[i][j]);
        }
        __syncthreads();
    }

#pragma unroll
    for (int i = 0; i < 4; i++) {
        int m = m0 + ty * 4 + i;
#pragma unroll
        for (int j = 0; j < 4; j++) {
            int n = n0 + tx * 4 + j;
            float v = acc[i][j] + bias[n];
            if (GELU) v = 0.5f * v * (1.f + erff(v * 0.70710678118654752f));
            if (RES)  v += res[(size_t)m * N + n];
            C[(size_t)m * N + n] = v;
        }
    }
}

// ---------------------------------------------------------------------------
// Spatial windowed attention: one block per token (packed (b*8+t)*1024+hw),
// one warp per head. 1 query vs 9 neighbors, DH=32 (one dim per lane).
// ---------------------------------------------------------------------------
__global__ __launch_bounds__(256)
void spatial_attn_kernel(const float* __restrict__ Q, const float* __restrict__ K,
                         const float* __restrict__ V, float* __restrict__ O)
{
    const int token = blockIdx.x;           // 0..32767
    const int head  = threadIdx.x >> 5;
    const int lane  = threadIdx.x & 31;
    const int hw = token & (HW_ - 1);
    const int r = hw >> 5, c = hw & 31;
    const size_t base = (size_t)token * D_MODEL + head * DH_;
    const float scale = 0.17677669529663687f;   // 1/sqrt(32)

    const float q = Q[base + lane];
    float sc[9];
    float mx = -1e30f;
#pragma unroll
    for (int n = 0; n < 9; n++) {
        int dr = n / 3 - 1, dc = n % 3 - 1;
        int rr = r + dr, cc = c + dc;
        bool ok = (rr >= 0) & (rr < 32) & (cc >= 0) & (cc < 32);
        float s = -1e9f;
        if (ok) {
            int t2 = token + dr * 32 + dc;
            float p = q * K[(size_t)t2 * D_MODEL + head * DH_ + lane];
#pragma unroll
            for (int o = 16; o; o >>= 1) p += __shfl_xor_sync(0xffffffffu, p, o);
            s = p * scale;
        }
        sc[n] = s;
        mx = fmaxf(mx, s);
    }
    float denom = 0.f;
#pragma unroll
    for (int n = 0; n < 9; n++) { sc[n] = expf(sc[n] - mx); denom += sc[n]; }
    float inv = 1.f / denom;

    float o_acc = 0.f;
#pragma unroll
    for (int n = 0; n < 9; n++) {
        int dr = n / 3 - 1, dc = n % 3 - 1;
        int rr = r + dr, cc = c + dc;
        bool ok = (rr >= 0) & (rr < 32) & (cc >= 0) & (cc < 32);
        if (ok) {
            int t2 = token + dr * 32 + dc;
            o_acc = fmaf(sc[n] * inv, V[(size_t)t2 * D_MODEL + head * DH_ + lane], o_acc);
        }
    }
    O[base + lane] = o_acc;
}

// ---------------------------------------------------------------------------
// Assemble x = concat(spatial_out + residual, last frame): full (B,9,HW,D)
// ---------------------------------------------------------------------------
__global__ void assemble_x_kernel(const float* __restrict__ query,
                                  const float* __restrict__ sp,
                                  float* __restrict__ x)
{
    size_t i = (size_t)blockIdx.x * blockDim.x + threadIdx.x;
    const int per_bt = HW_ * D_MODEL;
    int bt = (int)(i / per_bt);
    int rem = (int)(i % per_bt);
    int b = bt / TQ_, t = bt % TQ_;
    float v = query[i];
    if (t < TS_) v += sp[(size_t)(b * TS_ + t) * per_bt + rem];
    x[i] = v;
}

// ---------------------------------------------------------------------------
// Temporal RoPE attention: one block per (b,hw), one warp per head.
// T=9 sequence, DH=32 (one dim per lane). RoPE pairs via shfl_xor(...,16).
// ---------------------------------------------------------------------------
__global__ __launch_bounds__(256)
void temporal_attn_kernel(const float* __restrict__ Q, const float* __restrict__ K,
                          const float* __restrict__ V,
                          const unsigned char* __restrict__ mask,
                          float* __restrict__ O)
{
    const int seq  = blockIdx.x;        // 0..4095 = b*1024 + hw
    const int head = threadIdx.x >> 5;
    const int lane = threadIdx.x & 31;
    const int b  = seq >> 10;
    const int hw = seq & (HW_ - 1);
    const size_t tstride = (size_t)HW_ * D_MODEL;
    const size_t base0 = ((size_t)(b * TQ_) * HW_ + hw) * D_MODEL + head * DH_ + lane;
    const float scale = 0.17677669529663687f;

    const int pi = lane & 15;
    const float inv = powf(10000.f, -(float)pi / 16.f);

    float qv[9], kv[9], vv[9];
#pragma unroll
    for (int t = 0; t < TQ_; t++) {
        float qq = Q[base0 + t * tstride];
        float kk = K[base0 + t * tstride];
        vv[t]    = V[base0 + t * tstride];
        float ang = (float)t * inv;
        float cs = cosf(ang), sn = sinf(ang);
        float qp = __shfl_xor_sync(0xffffffffu, qq, 16);
        float kp = __shfl_xor_sync(0xffffffffu, kk, 16);
        if (lane < 16) {
            qv[t] = qq * cs - qp * sn;
            kv[t] = kk * cs - kp * sn;
        } else {
            qv[t] = qp * sn + qq * cs;
            kv[t] = kp * sn + kk * cs;
        }
    }

#pragma unroll
    for (int tq = 0; tq < TQ_; tq++) {
        float sc[9];
        float mx = -1e30f;
#pragma unroll
        for (int tk = 0; tk < TQ_; tk++) {
            float p = qv[tq] * kv[tk];
#pragma unroll
            for (int o = 16; o; o >>= 1) p += __shfl_xor_sync(0xffffffffu, p, o);
            float s = p * scale;
            if (mask[tq * TQ_ + tk]) s = -1e9f;
            sc[tk] = s;
            mx = fmaxf(mx, s);
        }
        float denom = 0.f;
#pragma unroll
        for (int tk = 0; tk < TQ_; tk++) { sc[tk] = expf(sc[tk] - mx); denom += sc[tk]; }
        float invd = 1.f / denom;
        float o_acc = 0.f;
#pragma unroll
        for (int tk = 0; tk < TQ_; tk++) o_acc = fmaf(sc[tk] * invd, vv[tk], o_acc);
        O[base0 + tq * tstride] = o_acc;
    }
}

// ---------------------------------------------------------------------------
// CLS frame averaging: x[:,0] = mean over HW, broadcast back (in place).
// One block per batch, one thread per channel.
// ---------------------------------------------------------------------------
__global__ void cls_avg_kernel(float* __restrict__ y)
{
    int b = blockIdx.x;
    int d = threadIdx.x;
    size_t base = (size_t)b * TQ_ * HW_ * D_MODEL;
    float s = 0.f;
    for (int hw = 0; hw < HW_; hw++) s += y[base + (size_t)hw * D_MODEL + d];
    float avg = s * (1.f / HW_);
    for (int hw = 0; hw < HW_; hw++) y[base + (size_t)hw * D_MODEL + d] = avg;
}

// ---------------------------------------------------------------------------

static inline void run_gemm(const float* A, const float* W, const float* bias,
                            const float* res, float* C, int M, int N, int K,
                            bool gelu, bool has_res)
{
    dim3 grid(N / 64, M / 64);
    if (gelu)
        gemm_kernel<true, false><<<grid, 256>>>(A, W, bias, nullptr, C, M, N, K);
    else if (has_res)
        gemm_kernel<false, true><<<grid, 256>>>(A, W, bias, res, C, M, N, K);
    else
        gemm_kernel<false, false><<<grid, 256>>>(A, W, bias, nullptr, C, M, N, K);
}

extern "C" void kernel_launch(void* const* d_in, const int* in_sizes, int n_in,
                              void* d_out, int out_size)
{
    const float* query = (const float*)d_in[0];
    const unsigned char* tmask = (const unsigned char*)d_in[2];
    const float* sln_g = (const float*)d_in[3];
    const float* sln_b = (const float*)d_in[4];
    const float* s_wq = (const float*)d_in[5];
    const float* s_bq = (const float*)d_in[6];
    const float* s_wk = (const float*)d_in[7];
    const float* s_bk = (const float*)d_in[8];
    const float* s_wv = (const float*)d_in[9];
    const float* s_bv = (const float*)d_in[10];
    const float* s_wo = (const float*)d_in[11];
    const float* s_bo = (const float*)d_in[12];
    const float* tln_g = (const float*)d_in[13];
    const float* tln_b = (const float*)d_in[14];
    const float* t_wq = (const float*)d_in[15];
    const float* t_bq = (const float*)d_in[16];
    const float* t_wk = (const float*)d_in[17];
    const float* t_bk = (const float*)d_in[18];
    const float* t_wv = (const float*)d_in[19];
    const float* t_bv = (const float*)d_in[20];
    const float* t_wo = (const float*)d_in[21];
    const float* t_bo = (const float*)d_in[22];
    const float* mln_g = (const float*)d_in[23];
    const float* mln_b = (const float*)d_in[24];
    const float* w1 = (const float*)d_in[25];
    const float* b1 = (const float*)d_in[26];
    const float* w2 = (const float*)d_in[27];
    const float* b2 = (const float*)d_in[28];
    float* out = (float*)d_out;

    float *ln, *q, *k, *v, *ao, *x, *y, *tmp, *hid;
    cudaGetSymbolAddress((void**)&ln,  g_ln);
    cudaGetSymbolAddress((void**)&q,   g_q);
    cudaGetSymbolAddress((void**)&k,   g_k);
    cudaGetSymbolAddress((void**)&v,   g_v);
    cudaGetSymbolAddress((void**)&ao,  g_ao);
    cudaGetSymbolAddress((void**)&x,   g_x);
    cudaGetSymbolAddress((void**)&y,   g_y);
    cudaGetSymbolAddress((void**)&tmp, g_tmp);
    cudaGetSymbolAddress((void**)&hid, g_hid);

    // ---- Stage A: spatial windowed attention (frames 0..7) ----
    // LN of spatial tokens (gather from query, skipping last frame per batch)
    ln_kernel<<<MS / 8, 256>>>(query, ln, sln_g, sln_b, MS, TQ_ * HW_, TS_ * HW_);
    run_gemm(ln, s_wq, s_bq, nullptr, q, MS, D_MODEL, D_MODEL, false, false);
    run_gemm(ln, s_wk, s_bk, nullptr, k, MS, D_MODEL, D_MODEL, false, false);
    run_gemm(ln, s_wv, s_bv, nullptr, v, MS, D_MODEL, D_MODEL, false, false);
    spatial_attn_kernel<<<MS, 256>>>(q, k, v, ao);
    run_gemm(ao, s_wo, s_bo, nullptr, tmp, MS, D_MODEL, D_MODEL, false, false);
    // x = [spatial_out + residual ; last frame]
    assemble_x_kernel<<<MT * D_MODEL / 256, 256>>>(query, tmp, x);

    // ---- Stage B: temporal RoPE attention ----
    ln_kernel<<<MT / 8, 256>>>(x, ln, tln_g, tln_b, MT, TQ_ * HW_, TQ_ * HW_);
    run_gemm(ln, t_wq, t_bq, nullptr, q, MT, D_MODEL, D_MODEL, false, false);
    run_gemm(ln, t_wk, t_bk, nullptr, k, MT, D_MODEL, D_MODEL, false, false);
    run_gemm(ln, t_wv, t_bv, nullptr, v, MT, D_MODEL, D_MODEL, false, false);
    temporal_attn_kernel<<<B_ * HW_, 256>>>(q, k, v, tmask, ao);
    run_gemm(ao, t_wo, t_bo, x, y, MT, D_MODEL, D_MODEL, false, true);

    // CLS frame averaging (in place on y)
    cls_avg_kernel<<<B_, D_MODEL>>>(y);

    // ---- Stage C: MLP ----
    ln_kernel<<<MT / 8, 256>>>(y, ln, mln_g, mln_b, MT, TQ_ * HW_, TQ_ * HW_);
    run_gemm(ln, w1, b1, nullptr, hid, MT, MLP_, D_MODEL, true, false);
    run_gemm(hid, w2, b2, y, out, MT, D_MODEL, MLP_, false, true);
}

// round 5
// speedup vs baseline: 2.3891x; 2.3891x over previous
#include <cuda_runtime.h>
#include <math.h>
#include <stdint.h>

// Problem constants
#define D_MODEL 256
#define B_      4
#define TQ_     9
#define TS_     8
#define HW_     1024
#define NH_     8
#define DH_     32
#define MLP_    1024

static const int MS = B_ * TS_ * HW_;   // 32768 spatial tokens
static const int MT = B_ * TQ_ * HW_;   // 36864 full tokens

// Scratch (device globals — no allocations allowed)
__device__ float g_ln [MT * D_MODEL];
__device__ float g_q  [MT * D_MODEL];
__device__ float g_k  [MT * D_MODEL];
__device__ float g_v  [MT * D_MODEL];
__device__ float g_ao [MT * D_MODEL];
__device__ float g_x  [MT * D_MODEL];
__device__ float g_y  [MT * D_MODEL];
__device__ float g_tmp[MT * D_MODEL];
__device__ float g_hid[MT * MLP_];

// ---------------------------------------------------------------------------
// LayerNorm: one warp per token, 8 elems/lane (D=256)
// ---------------------------------------------------------------------------
__global__ void ln_kernel(const float* __restrict__ src, float* __restrict__ dst,
                          const float* __restrict__ gam, const float* __restrict__ bet,
                          int M, int src_tpb, int dst_tpb)
{
    int warp = (blockIdx.x * blockDim.x + threadIdx.x) >> 5;
    int lane = threadIdx.x & 31;
    if (warp >= M) return;
    int bb = warp / dst_tpb;
    int rem = warp % dst_tpb;
    const float* x = src + ((size_t)bb * src_tpb + rem) * D_MODEL;

    float vals[8];
    float s = 0.f, s2 = 0.f;
#pragma unroll
    for (int j = 0; j < 8; j++) {
        float v = x[lane + 32 * j];
        vals[j] = v; s += v; s2 += v * v;
    }
#pragma unroll
    for (int o = 16; o; o >>= 1) {
        s  += __shfl_xor_sync(0xffffffffu, s,  o);
        s2 += __shfl_xor_sync(0xffffffffu, s2, o);
    }
    float mean = s * (1.f / D_MODEL);
    float var  = s2 * (1.f / D_MODEL) - mean * mean;
    float rstd = rsqrtf(var + 1e-5f);

    float* y = dst + (size_t)warp * D_MODEL;
#pragma unroll
    for (int j = 0; j < 8; j++) {
        int d = lane + 32 * j;
        y[d] = (vals[j] - mean) * rstd * gam[d] + bet[d];
    }
}

// ---------------------------------------------------------------------------
// tf32 tensor-core GEMM: C[M,N] = A[M,K] @ W[K,N] + bias (+ GELU / residual)
// Block 128x128, BK=16, 256 threads (8 warps, 2x4), warp tile 64x32,
// mma.sync.m16n8k8 tf32 with fp32 accumulate. Reg-staged double buffering.
// fp32 -> tf32 via cvt.rna at smem-store time (unbiased rounding).
// ---------------------------------------------------------------------------
#define BM 128
#define BN 128
#define BKG 16

__device__ __forceinline__ uint32_t f2tf32(float f) {
    uint32_t u;
    asm("cvt.rna.tf32.f32 %0, %1;" : "=r"(u) : "f"(f));
    return u;
}

__device__ __forceinline__ void mma_tf32(float* d, const uint32_t* a, const uint32_t* b) {
    asm volatile(
        "mma.sync.aligned.m16n8k8.row.col.f32.tf32.tf32.f32 "
        "{%0,%1,%2,%3}, {%4,%5,%6,%7}, {%8,%9}, {%0,%1,%2,%3};"
        : "+f"(d[0]), "+f"(d[1]), "+f"(d[2]), "+f"(d[3])
        : "r"(a[0]), "r"(a[1]), "r"(a[2]), "r"(a[3]), "r"(b[0]), "r"(b[1]));
}

template <bool GELU, bool RES>
__global__ __launch_bounds__(256)
void gemm_tc_kernel(const float* __restrict__ A, const float* __restrict__ W,
                    const float* __restrict__ bias, const float* __restrict__ res,
                    float* __restrict__ C, int M, int N, int K)
{
    __shared__ uint32_t As[BM][BKG + 4];    // stride 20: conflict-free frag loads
    __shared__ uint32_t Bs[BKG][BN + 8];    // stride 136: conflict-free frag loads

    const int tid  = threadIdx.x;
    const int lane = tid & 31;
    const int warp = tid >> 5;
    const int wm   = warp & 1;     // 2 warps in M
    const int wn   = warp >> 1;    // 4 warps in N
    const int m0 = blockIdx.y * BM;
    const int n0 = blockIdx.x * BN;
    const int wmo = wm * 64;
    const int wno = wn * 32;

    // staging indices: A tile 128x16 floats (512 float4), B tile 16x128 (512 float4)
    const int aIdx0 = tid, aIdx1 = tid + 256;
    const int ar0 = aIdx0 >> 2, ac0 = (aIdx0 & 3) * 4;
    const int ar1 = aIdx1 >> 2, ac1 = (aIdx1 & 3) * 4;
    const int br0 = aIdx0 >> 5, bc0 = (aIdx0 & 31) * 4;
    const int br1 = aIdx1 >> 5, bc1 = (aIdx1 & 31) * 4;

    float acc[4][4][4];
#pragma unroll
    for (int i = 0; i < 4; i++)
#pragma unroll
        for (int j = 0; j < 4; j++)
#pragma unroll
            for (int r = 0; r < 4; r++) acc[i][j][r] = 0.f;

    float4 sa0, sa1, sb0, sb1;

    // prologue: load first stage
    sa0 = *(const float4*)&A[(size_t)(m0 + ar0) * K + ac0];
    sa1 = *(const float4*)&A[(size_t)(m0 + ar1) * K + ac1];
    sb0 = *(const float4*)&W[(size_t)br0 * N + n0 + bc0];
    sb1 = *(const float4*)&W[(size_t)br1 * N + n0 + bc1];

    auto store_stage = [&]() {
        As[ar0][(ac0) + 0] = f2tf32(sa0.x); As[ar0][(ac0) + 1] = f2tf32(sa0.y);
        As[ar0][(ac0) + 2] = f2tf32(sa0.z); As[ar0][(ac0) + 3] = f2tf32(sa0.w);
        As[ar1][(ac1) + 0] = f2tf32(sa1.x); As[ar1][(ac1) + 1] = f2tf32(sa1.y);
        As[ar1][(ac1) + 2] = f2tf32(sa1.z); As[ar1][(ac1) + 3] = f2tf32(sa1.w);
        Bs[br0][(bc0) + 0] = f2tf32(sb0.x); Bs[br0][(bc0) + 1] = f2tf32(sb0.y);
        Bs[br0][(bc0) + 2] = f2tf32(sb0.z); Bs[br0][(bc0) + 3] = f2tf32(sb0.w);
        Bs[br1][(bc1) + 0] = f2tf32(sb1.x); Bs[br1][(bc1) + 1] = f2tf32(sb1.y);
        Bs[br1][(bc1) + 2] = f2tf32(sb1.z); Bs[br1][(bc1) + 3] = f2tf32(sb1.w);
    };

    auto compute_stage = [&]() {
#pragma unroll
        for (int ks = 0; ks < BKG; ks += 8) {
            uint32_t afr[4][4];
            uint32_t bfr[4][2];
#pragma unroll
            for (int mt = 0; mt < 4; mt++) {
                int r = wmo + mt * 16 + (lane >> 2);
                int c = ks + (lane & 3);
                afr[mt][0] = As[r][c];
                afr[mt][1] = As[r + 8][c];
                afr[mt][2] = As[r][c + 4];
                afr[mt][3] = As[r + 8][c + 4];
            }
#pragma unroll
            for (int nt = 0; nt < 4; nt++) {
                int bn = wno + nt * 8 + (lane >> 2);
                int bk = ks + (lane & 3);
                bfr[nt][0] = Bs[bk][bn];
                bfr[nt][1] = Bs[bk + 4][bn];
            }
#pragma unroll
            for (int mt = 0; mt < 4; mt++)
#pragma unroll
                for (int nt = 0; nt < 4; nt++)
                    mma_tf32(acc[mt][nt], afr[mt], bfr[nt]);
        }
    };

    store_stage();
    __syncthreads();

    for (int k0 = BKG; k0 < K; k0 += BKG) {
        // load next stage into regs
        sa0 = *(const float4*)&A[(size_t)(m0 + ar0) * K + k0 + ac0];
        sa1 = *(const float4*)&A[(size_t)(m0 + ar1) * K + k0 + ac1];
        sb0 = *(const float4*)&W[(size_t)(k0 + br0) * N + n0 + bc0];
        sb1 = *(const float4*)&W[(size_t)(k0 + br1) * N + n0 + bc1];

        compute_stage();
        __syncthreads();
        store_stage();
        __syncthreads();
    }
    compute_stage();

    // epilogue
#pragma unroll
    for (int mt = 0; mt < 4; mt++) {
#pragma unroll
        for (int nt = 0; nt < 4; nt++) {
            int row0 = m0 + wmo + mt * 16 + (lane >> 2);
            int col0 = n0 + wno + nt * 8 + 2 * (lane & 3);
#pragma unroll
            for (int r = 0; r < 4; r++) {
                int row = row0 + (r >> 1) * 8;
                int col = col0 + (r & 1);
                float v = acc[mt][nt][r] + bias[col];
                if (GELU) v = 0.5f * v * (1.f + erff(v * 0.70710678118654752f));
                if (RES)  v += res[(size_t)row * N + col];
                C[(size_t)row * N + col] = v;
            }
        }
    }
}

// ---------------------------------------------------------------------------
// Spatial windowed attention: one block per token, one warp per head.
// ---------------------------------------------------------------------------
__global__ __launch_bounds__(256)
void spatial_attn_kernel(const float* __restrict__ Q, const float* __restrict__ K,
                         const float* __restrict__ V, float* __restrict__ O)
{
    const int token = blockIdx.x;           // 0..32767
    const int head  = threadIdx.x >> 5;
    const int lane  = threadIdx.x & 31;
    const int hw = token & (HW_ - 1);
    const int r = hw >> 5, c = hw & 31;
    const size_t base = (size_t)token * D_MODEL + head * DH_;
    const float scale = 0.17677669529663687f;   // 1/sqrt(32)

    const float q = Q[base + lane];
    float sc[9];
    float mx = -1e30f;
#pragma unroll
    for (int n = 0; n < 9; n++) {
        int dr = n / 3 - 1, dc = n % 3 - 1;
        int rr = r + dr, cc = c + dc;
        bool ok = (rr >= 0) & (rr < 32) & (cc >= 0) & (cc < 32);
        float s = -1e9f;
        if (ok) {
            int t2 = token + dr * 32 + dc;
            float p = q * K[(size_t)t2 * D_MODEL + head * DH_ + lane];
#pragma unroll
            for (int o = 16; o; o >>= 1) p += __shfl_xor_sync(0xffffffffu, p, o);
            s = p * scale;
        }
        sc[n] = s;
        mx = fmaxf(mx, s);
    }
    float denom = 0.f;
#pragma unroll
    for (int n = 0; n < 9; n++) { sc[n] = expf(sc[n] - mx); denom += sc[n]; }
    float inv = 1.f / denom;

    float o_acc = 0.f;
#pragma unroll
    for (int n = 0; n < 9; n++) {
        int dr = n / 3 - 1, dc = n % 3 - 1;
        int rr = r + dr, cc = c + dc;
        bool ok = (rr >= 0) & (rr < 32) & (cc >= 0) & (cc < 32);
        if (ok) {
            int t2 = token + dr * 32 + dc;
            o_acc = fmaf(sc[n] * inv, V[(size_t)t2 * D_MODEL + head * DH_ + lane], o_acc);
        }
    }
    O[base + lane] = o_acc;
}

// ---------------------------------------------------------------------------
// Assemble x = concat(spatial_out + residual, last frame)
// ---------------------------------------------------------------------------
__global__ void assemble_x_kernel(const float* __restrict__ query,
                                  const float* __restrict__ sp,
                                  float* __restrict__ x)
{
    size_t i = (size_t)blockIdx.x * blockDim.x + threadIdx.x;
    const int per_bt = HW_ * D_MODEL;
    int bt = (int)(i / per_bt);
    int rem = (int)(i % per_bt);
    int b = bt / TQ_, t = bt % TQ_;
    float v = query[i];
    if (t < TS_) v += sp[(size_t)(b * TS_ + t) * per_bt + rem];
    x[i] = v;
}

// ---------------------------------------------------------------------------
// Temporal RoPE attention
// ---------------------------------------------------------------------------
__global__ __launch_bounds__(256)
void temporal_attn_kernel(const float* __restrict__ Q, const float* __restrict__ K,
                          const float* __restrict__ V,
                          const unsigned char* __restrict__ mask,
                          float* __restrict__ O)
{
    const int seq  = blockIdx.x;        // b*1024 + hw
    const int head = threadIdx.x >> 5;
    const int lane = threadIdx.x & 31;
    const int b  = seq >> 10;
    const int hw = seq & (HW_ - 1);
    const size_t tstride = (size_t)HW_ * D_MODEL;
    const size_t base0 = ((size_t)(b * TQ_) * HW_ + hw) * D_MODEL + head * DH_ + lane;
    const float scale = 0.17677669529663687f;

    const int pi = lane & 15;
    const float inv = powf(10000.f, -(float)pi / 16.f);

    float qv[9], kv[9], vv[9];
#pragma unroll
    for (int t = 0; t < TQ_; t++) {
        float qq = Q[base0 + t * tstride];
        float kk = K[base0 + t * tstride];
        vv[t]    = V[base0 + t * tstride];
        float ang = (float)t * inv;
        float cs = cosf(ang), sn = sinf(ang);
        float qp = __shfl_xor_sync(0xffffffffu, qq, 16);
        float kp = __shfl_xor_sync(0xffffffffu, kk, 16);
        if (lane < 16) {
            qv[t] = qq * cs - qp * sn;
            kv[t] = kk * cs - kp * sn;
        } else {
            qv[t] = qp * sn + qq * cs;
            kv[t] = kp * sn + kk * cs;
        }
    }

#pragma unroll
    for (int tq = 0; tq < TQ_; tq++) {
        float sc[9];
        float mx = -1e30f;
#pragma unroll
        for (int tk = 0; tk < TQ_; tk++) {
            float p = qv[tq] * kv[tk];
#pragma unroll
            for (int o = 16; o; o >>= 1) p += __shfl_xor_sync(0xffffffffu, p, o);
            float s = p * scale;
            if (mask[tq * TQ_ + tk]) s = -1e9f;
            sc[tk] = s;
            mx = fmaxf(mx, s);
        }
        float denom = 0.f;
#pragma unroll
        for (int tk = 0; tk < TQ_; tk++) { sc[tk] = expf(sc[tk] - mx); denom += sc[tk]; }
        float invd = 1.f / denom;
        float o_acc = 0.f;
#pragma unroll
        for (int tk = 0; tk < TQ_; tk++) o_acc = fmaf(sc[tk] * invd, vv[tk], o_acc);
        O[base0 + tq * tstride] = o_acc;
    }
}

// ---------------------------------------------------------------------------
// CLS frame averaging
// ---------------------------------------------------------------------------
__global__ void cls_avg_kernel(float* __restrict__ y)
{
    int b = blockIdx.x;
    int d = threadIdx.x;
    size_t base = (size_t)b * TQ_ * HW_ * D_MODEL;
    float s = 0.f;
    for (int hw = 0; hw < HW_; hw++) s += y[base + (size_t)hw * D_MODEL + d];
    float avg = s * (1.f / HW_);
    for (int hw = 0; hw < HW_; hw++) y[base + (size_t)hw * D_MODEL + d] = avg;
}

// ---------------------------------------------------------------------------

static inline void run_gemm(const float* A, const float* W, const float* bias,
                            const float* res, float* C, int M, int N, int K,
                            bool gelu, bool has_res)
{
    dim3 grid(N / BN, M / BM);
    if (gelu)
        gemm_tc_kernel<true, false><<<grid, 256>>>(A, W, bias, nullptr, C, M, N, K);
    else if (has_res)
        gemm_tc_kernel<false, true><<<grid, 256>>>(A, W, bias, res, C, M, N, K);
    else
        gemm_tc_kernel<false, false><<<grid, 256>>>(A, W, bias, nullptr, C, M, N, K);
}

extern "C" void kernel_launch(void* const* d_in, const int* in_sizes, int n_in,
                              void* d_out, int out_size)
{
    const float* query = (const float*)d_in[0];
    const unsigned char* tmask = (const unsigned char*)d_in[2];
    const float* sln_g = (const float*)d_in[3];
    const float* sln_b = (const float*)d_in[4];
    const float* s_wq = (const float*)d_in[5];
    const float* s_bq = (const float*)d_in[6];
    const float* s_wk = (const float*)d_in[7];
    const float* s_bk = (const float*)d_in[8];
    const float* s_wv = (const float*)d_in[9];
    const float* s_bv = (const float*)d_in[10];
    const float* s_wo = (const float*)d_in[11];
    const float* s_bo = (const float*)d_in[12];
    const float* tln_g = (const float*)d_in[13];
    const float* tln_b = (const float*)d_in[14];
    const float* t_wq = (const float*)d_in[15];
    const float* t_bq = (const float*)d_in[16];
    const float* t_wk = (const float*)d_in[17];
    const float* t_bk = (const float*)d_in[18];
    const float* t_wv = (const float*)d_in[19];
    const float* t_bv = (const float*)d_in[20];
    const float* t_wo = (const float*)d_in[21];
    const float* t_bo = (const float*)d_in[22];
    const float* mln_g = (const float*)d_in[23];
    const float* mln_b = (const float*)d_in[24];
    const float* w1 = (const float*)d_in[25];
    const float* b1 = (const float*)d_in[26];
    const float* w2 = (const float*)d_in[27];
    const float* b2 = (const float*)d_in[28];
    float* out = (float*)d_out;

    float *ln, *q, *k, *v, *ao, *x, *y, *tmp, *hid;
    cudaGetSymbolAddress((void**)&ln,  g_ln);
    cudaGetSymbolAddress((void**)&q,   g_q);
    cudaGetSymbolAddress((void**)&k,   g_k);
    cudaGetSymbolAddress((void**)&v,   g_v);
    cudaGetSymbolAddress((void**)&ao,  g_ao);
    cudaGetSymbolAddress((void**)&x,   g_x);
    cudaGetSymbolAddress((void**)&y,   g_y);
    cudaGetSymbolAddress((void**)&tmp, g_tmp);
    cudaGetSymbolAddress((void**)&hid, g_hid);

    // ---- Stage A: spatial windowed attention (frames 0..7) ----
    ln_kernel<<<MS / 8, 256>>>(query, ln, sln_g, sln_b, MS, TQ_ * HW_, TS_ * HW_);
    run_gemm(ln, s_wq, s_bq, nullptr, q, MS, D_MODEL, D_MODEL, false, false);
    run_gemm(ln, s_wk, s_bk, nullptr, k, MS, D_MODEL, D_MODEL, false, false);
    run_gemm(ln, s_wv, s_bv, nullptr, v, MS, D_MODEL, D_MODEL, false, false);
    spatial_attn_kernel<<<MS, 256>>>(q, k, v, ao);
    run_gemm(ao, s_wo, s_bo, nullptr, tmp, MS, D_MODEL, D_MODEL, false, false);
    assemble_x_kernel<<<MT * D_MODEL / 256, 256>>>(query, tmp, x);

    // ---- Stage B: temporal RoPE attention ----
    ln_kernel<<<MT / 8, 256>>>(x, ln, tln_g, tln_b, MT, TQ_ * HW_, TQ_ * HW_);
    run_gemm(ln, t_wq, t_bq, nullptr, q, MT, D_MODEL, D_MODEL, false, false);
    run_gemm(ln, t_wk, t_bk, nullptr, k, MT, D_MODEL, D_MODEL, false, false);
    run_gemm(ln, t_wv, t_bv, nullptr, v, MT, D_MODEL, D_MODEL, false, false);
    temporal_attn_kernel<<<B_ * HW_, 256>>>(q, k, v, tmask, ao);
    run_gemm(ao, t_wo, t_bo, x, y, MT, D_MODEL, D_MODEL, false, true);

    // CLS frame averaging (in place on y)
    cls_avg_kernel<<<B_, D_MODEL>>>(y);

    // ---- Stage C: MLP ----
    ln_kernel<<<MT / 8, 256>>>(y, ln, mln_g, mln_b, MT, TQ_ * HW_, TQ_ * HW_);
    run_gemm(ln, w1, b1, nullptr, hid, MT, MLP_, D_MODEL, true, false);
    run_gemm(hid, w2, b2, y, out, MT, D_MODEL, MLP_, false, true);
}

// round 6
// speedup vs baseline: 3.2002x; 1.3395x over previous
#include <cuda_runtime.h>
#include <cuda_bf16.h>
#include <math.h>
#include <stdint.h>

// Problem constants
#define D_MODEL 256
#define B_      4
#define TQ_     9
#define TS_     8
#define HW_     1024
#define NH_     8
#define DH_     32
#define MLP_    1024

static const int MS = B_ * TS_ * HW_;   // 32768 spatial tokens
static const int MT = B_ * TQ_ * HW_;   // 36864 full tokens

// Scratch (device globals — no allocations allowed)
__device__ __nv_bfloat16 g_lnb [MT * D_MODEL];
__device__ float         g_qkv [MT * 768];
__device__ __nv_bfloat16 g_aob [MT * D_MODEL];
__device__ float         g_x   [MT * D_MODEL];
__device__ float         g_y   [MT * D_MODEL];
__device__ float         g_tmp [MT * D_MODEL];
__device__ __nv_bfloat16 g_hidb[MT * MLP_];
// packed bf16 weights
__device__ __nv_bfloat16 g_wsp[D_MODEL * 768];
__device__ __nv_bfloat16 g_wtp[D_MODEL * 768];
__device__ __nv_bfloat16 g_wso[D_MODEL * D_MODEL];
__device__ __nv_bfloat16 g_wto[D_MODEL * D_MODEL];
__device__ __nv_bfloat16 g_w1 [D_MODEL * MLP_];
__device__ __nv_bfloat16 g_w2 [MLP_ * D_MODEL];
__device__ float g_bsp[768];
__device__ float g_btp[768];

// ---------------------------------------------------------------------------
// Weight convert/pack kernels (tiny prologue work)
// ---------------------------------------------------------------------------
__global__ void cvt_pack_kernel(const float* __restrict__ src, __nv_bfloat16* __restrict__ dst,
                                int total, int Nsrc, int Ndst, int colOff)
{
    int i = blockIdx.x * blockDim.x + threadIdx.x;
    if (i >= total) return;
    int k = i / Nsrc, n = i - k * Nsrc;
    dst[(size_t)k * Ndst + colOff + n] = __float2bfloat16(src[i]);
}

__global__ void pack_bias_kernel(const float* __restrict__ s, float* __restrict__ d, int n, int off)
{
    int i = blockIdx.x * blockDim.x + threadIdx.x;
    if (i < n) d[off + i] = s[i];
}

// ---------------------------------------------------------------------------
// LayerNorm: one warp per token, 8 elems/lane (D=256), bf16 output
// ---------------------------------------------------------------------------
__global__ void ln_kernel(const float* __restrict__ src, __nv_bfloat16* __restrict__ dst,
                          const float* __restrict__ gam, const float* __restrict__ bet,
                          int M, int src_tpb, int dst_tpb)
{
    int warp = (blockIdx.x * blockDim.x + threadIdx.x) >> 5;
    int lane = threadIdx.x & 31;
    if (warp >= M) return;
    int bb = warp / dst_tpb;
    int rem = warp % dst_tpb;
    const float* x = src + ((size_t)bb * src_tpb + rem) * D_MODEL;

    float vals[8];
    float s = 0.f, s2 = 0.f;
#pragma unroll
    for (int j = 0; j < 8; j++) {
        float v = x[lane + 32 * j];
        vals[j] = v; s += v; s2 += v * v;
    }
#pragma unroll
    for (int o = 16; o; o >>= 1) {
        s  += __shfl_xor_sync(0xffffffffu, s,  o);
        s2 += __shfl_xor_sync(0xffffffffu, s2, o);
    }
    float mean = s * (1.f / D_MODEL);
    float var  = s2 * (1.f / D_MODEL) - mean * mean;
    float rstd = rsqrtf(var + 1e-5f);

    __nv_bfloat16* y = dst + (size_t)warp * D_MODEL;
#pragma unroll
    for (int j = 0; j < 8; j++) {
        int d = lane + 32 * j;
        y[d] = __float2bfloat16((vals[j] - mean) * rstd * gam[d] + bet[d]);
    }
}

// ---------------------------------------------------------------------------
// bf16 tensor-core GEMM: C[M,N] = A[M,K] @ W[K,N] + bias (+ GELU / residual)
// Block 128x128, BK=32, 256 threads (8 warps, 2x4 -> 64x32 warp tiles).
// cp.async double-buffered smem, ldmatrix fragments, mma.m16n8k16.bf16.
// ---------------------------------------------------------------------------
#define BM 128
#define BN 128
#define BKB 32
#define A_PAD 40
#define B_PAD 136

#define CP_ASYNC16(dst_u32, src_ptr) \
    asm volatile("cp.async.cg.shared.global [%0], [%1], 16;\n" :: "r"(dst_u32), "l"(src_ptr))
#define CP_COMMIT() asm volatile("cp.async.commit_group;\n" ::: "memory")
#define CP_WAIT0()  asm volatile("cp.async.wait_group 0;\n" ::: "memory")

__device__ __forceinline__ void ldmx4(uint32_t& r0, uint32_t& r1, uint32_t& r2, uint32_t& r3,
                                      const void* p)
{
    uint32_t a = (uint32_t)__cvta_generic_to_shared(p);
    asm volatile("ldmatrix.sync.aligned.m8n8.x4.shared.b16 {%0,%1,%2,%3}, [%4];"
                 : "=r"(r0), "=r"(r1), "=r"(r2), "=r"(r3) : "r"(a));
}
__device__ __forceinline__ void ldmx4t(uint32_t& r0, uint32_t& r1, uint32_t& r2, uint32_t& r3,
                                       const void* p)
{
    uint32_t a = (uint32_t)__cvta_generic_to_shared(p);
    asm volatile("ldmatrix.sync.aligned.m8n8.x4.trans.shared.b16 {%0,%1,%2,%3}, [%4];"
                 : "=r"(r0), "=r"(r1), "=r"(r2), "=r"(r3) : "r"(a));
}
__device__ __forceinline__ void mma_bf16(float* d, const uint32_t* a, const uint32_t* b)
{
    asm volatile(
        "mma.sync.aligned.m16n8k16.row.col.f32.bf16.bf16.f32 "
        "{%0,%1,%2,%3}, {%4,%5,%6,%7}, {%8,%9}, {%0,%1,%2,%3};"
        : "+f"(d[0]), "+f"(d[1]), "+f"(d[2]), "+f"(d[3])
        : "r"(a[0]), "r"(a[1]), "r"(a[2]), "r"(a[3]), "r"(b[0]), "r"(b[1]));
}

__device__ __forceinline__ void storeC(float* p, float v)          { *p = v; }
__device__ __forceinline__ void storeC(__nv_bfloat16* p, float v)  { *p = __float2bfloat16(v); }

template <typename OutT, bool GELU, bool RES>
__global__ __launch_bounds__(256)
void gemm_bf16_kernel(const __nv_bfloat16* __restrict__ A, const __nv_bfloat16* __restrict__ W,
                      const float* __restrict__ bias, const float* __restrict__ res,
                      OutT* __restrict__ C, int M, int N, int K)
{
    __shared__ __nv_bfloat16 As[2][BM][A_PAD];
    __shared__ __nv_bfloat16 Bs[2][BKB][B_PAD];

    const int tid  = threadIdx.x;
    const int lane = tid & 31;
    const int warp = tid >> 5;
    const int wm   = warp & 1;
    const int wn   = warp >> 1;
    const int m0 = blockIdx.y * BM;
    const int n0 = blockIdx.x * BN;
    const int wmo = wm * 64;
    const int wno = wn * 32;

    // staging: A tile 128x32 bf16 = 512 x 16B chunks; B tile 32x128 = 512 chunks
    const int aR0 = tid >> 2,           aC0 = (tid & 3) * 8;
    const int aR1 = (tid + 256) >> 2,   aC1 = aC0;
    const int bR0 = tid >> 4,           bC0 = (tid & 15) * 8;
    const int bR1 = (tid + 256) >> 4,   bC1 = bC0;

    float acc[4][4][4];
#pragma unroll
    for (int i = 0; i < 4; i++)
#pragma unroll
        for (int j = 0; j < 4; j++)
#pragma unroll
            for (int r = 0; r < 4; r++) acc[i][j][r] = 0.f;

    auto load_tiles = [&](int buf, int k0) {
        CP_ASYNC16((uint32_t)__cvta_generic_to_shared(&As[buf][aR0][aC0]),
                   A + (size_t)(m0 + aR0) * K + k0 + aC0);
        CP_ASYNC16((uint32_t)__cvta_generic_to_shared(&As[buf][aR1][aC1]),
                   A + (size_t)(m0 + aR1) * K + k0 + aC1);
        CP_ASYNC16((uint32_t)__cvta_generic_to_shared(&Bs[buf][bR0][bC0]),
                   W + (size_t)(k0 + bR0) * N + n0 + bC0);
        CP_ASYNC16((uint32_t)__cvta_generic_to_shared(&Bs[buf][bR1][bC1]),
                   W + (size_t)(k0 + bR1) * N + n0 + bC1);
    };

    auto compute_stage = [&](int buf) {
#pragma unroll
        for (int ks = 0; ks < BKB; ks += 16) {
            uint32_t af[4][4];
            uint32_t bf[4][2];
#pragma unroll
            for (int mt = 0; mt < 4; mt++) {
                ldmx4(af[mt][0], af[mt][1], af[mt][2], af[mt][3],
                      &As[buf][wmo + mt * 16 + (lane & 15)][ks + (lane >> 4) * 8]);
            }
#pragma unroll
            for (int ng = 0; ng < 2; ng++) {
                uint32_t t0, t1, t2, t3;
                ldmx4t(t0, t1, t2, t3,
                       &Bs[buf][ks + (lane & 15)][wno + ng * 16 + (lane >> 4) * 8]);
                bf[ng * 2][0] = t0; bf[ng * 2][1] = t1;
                bf[ng * 2 + 1][0] = t2; bf[ng * 2 + 1][1] = t3;
            }
#pragma unroll
            for (int mt = 0; mt < 4; mt++)
#pragma unroll
                for (int nt = 0; nt < 4; nt++)
                    mma_bf16(acc[mt][nt], af[mt], bf[nt]);
        }
    };

    const int niter = K / BKB;
    load_tiles(0, 0);
    CP_COMMIT();

    for (int i = 0; i < niter; i++) {
        CP_WAIT0();
        __syncthreads();
        if (i + 1 < niter) { load_tiles((i + 1) & 1, (i + 1) * BKB); CP_COMMIT(); }
        compute_stage(i & 1);
        __syncthreads();
    }

    // epilogue
#pragma unroll
    for (int mt = 0; mt < 4; mt++) {
#pragma unroll
        for (int nt = 0; nt < 4; nt++) {
            int row0 = m0 + wmo + mt * 16 + (lane >> 2);
            int col0 = n0 + wno + nt * 8 + 2 * (lane & 3);
#pragma unroll
            for (int r = 0; r < 4; r++) {
                int row = row0 + (r >> 1) * 8;
                int col = col0 + (r & 1);
                float v = acc[mt][nt][r] + bias[col];
                if (GELU) v = 0.5f * v * (1.f + erff(v * 0.70710678118654752f));
                if (RES)  v += res[(size_t)row * N + col];
                storeC(&C[(size_t)row * N + col], v);
            }
        }
    }
}

// ---------------------------------------------------------------------------
// Spatial windowed attention: packed QKV (stride 768), bf16 output
// ---------------------------------------------------------------------------
__global__ __launch_bounds__(256)
void spatial_attn_kernel(const float* __restrict__ QKV, __nv_bfloat16* __restrict__ O)
{
    const int token = blockIdx.x;           // 0..32767
    const int head  = threadIdx.x >> 5;
    const int lane  = threadIdx.x & 31;
    const int hw = token & (HW_ - 1);
    const int r = hw >> 5, c = hw & 31;
    const size_t base = (size_t)token * 768 + head * DH_ + lane;
    const float scale = 0.17677669529663687f;   // 1/sqrt(32)

    const float q = QKV[base];
    float sc[9];
    float mx = -1e30f;
#pragma unroll
    for (int n = 0; n < 9; n++) {
        int dr = n / 3 - 1, dc = n % 3 - 1;
        int rr = r + dr, cc = c + dc;
        bool ok = (rr >= 0) & (rr < 32) & (cc >= 0) & (cc < 32);
        float s = -1e9f;
        if (ok) {
            int t2 = token + dr * 32 + dc;
            float p = q * QKV[(size_t)t2 * 768 + 256 + head * DH_ + lane];
#pragma unroll
            for (int o = 16; o; o >>= 1) p += __shfl_xor_sync(0xffffffffu, p, o);
            s = p * scale;
        }
        sc[n] = s;
        mx = fmaxf(mx, s);
    }
    float denom = 0.f;
#pragma unroll
    for (int n = 0; n < 9; n++) { sc[n] = expf(sc[n] - mx); denom += sc[n]; }
    float inv = 1.f / denom;

    float o_acc = 0.f;
#pragma unroll
    for (int n = 0; n < 9; n++) {
        int dr = n / 3 - 1, dc = n % 3 - 1;
        int rr = r + dr, cc = c + dc;
        bool ok = (rr >= 0) & (rr < 32) & (cc >= 0) & (cc < 32);
        if (ok) {
            int t2 = token + dr * 32 + dc;
            o_acc = fmaf(sc[n] * inv, QKV[(size_t)t2 * 768 + 512 + head * DH_ + lane], o_acc);
        }
    }
    O[(size_t)token * D_MODEL + head * DH_ + lane] = __float2bfloat16(o_acc);
}

// ---------------------------------------------------------------------------
// Assemble x = concat(spatial_out + residual, last frame)
// ---------------------------------------------------------------------------
__global__ void assemble_x_kernel(const float* __restrict__ query,
                                  const float* __restrict__ sp,
                                  float* __restrict__ x)
{
    size_t i = (size_t)blockIdx.x * blockDim.x + threadIdx.x;
    const int per_bt = HW_ * D_MODEL;
    int bt = (int)(i / per_bt);
    int rem = (int)(i % per_bt);
    int b = bt / TQ_, t = bt % TQ_;
    float v = query[i];
    if (t < TS_) v += sp[(size_t)(b * TS_ + t) * per_bt + rem];
    x[i] = v;
}

// ---------------------------------------------------------------------------
// Temporal RoPE attention: packed QKV (stride 768), bf16 output
// ---------------------------------------------------------------------------
__global__ __launch_bounds__(256)
void temporal_attn_kernel(const float* __restrict__ QKV,
                          const unsigned char* __restrict__ mask,
                          __nv_bfloat16* __restrict__ O)
{
    const int seq  = blockIdx.x;        // b*1024 + hw
    const int head = threadIdx.x >> 5;
    const int lane = threadIdx.x & 31;
    const int b  = seq >> 10;
    const int hw = seq & (HW_ - 1);
    const size_t tstride = (size_t)HW_ * 768;
    const size_t base0 = ((size_t)(b * TQ_) * HW_ + hw) * 768 + head * DH_ + lane;
    const size_t ostride = (size_t)HW_ * D_MODEL;
    const size_t obase = ((size_t)(b * TQ_) * HW_ + hw) * D_MODEL + head * DH_ + lane;
    const float scale = 0.17677669529663687f;

    const int pi = lane & 15;
    const float inv = powf(10000.f, -(float)pi / 16.f);

    float qv[9], kv[9], vv[9];
#pragma unroll
    for (int t = 0; t < TQ_; t++) {
        float qq = QKV[base0 + t * tstride];
        float kk = QKV[base0 + 256 + t * tstride];
        vv[t]    = QKV[base0 + 512 + t * tstride];
        float ang = (float)t * inv;
        float cs = cosf(ang), sn = sinf(ang);
        float qp = __shfl_xor_sync(0xffffffffu, qq, 16);
        float kp = __shfl_xor_sync(0xffffffffu, kk, 16);
        if (lane < 16) {
            qv[t] = qq * cs - qp * sn;
            kv[t] = kk * cs - kp * sn;
        } else {
            qv[t] = qp * sn + qq * cs;
            kv[t] = kp * sn + kk * cs;
        }
    }

#pragma unroll
    for (int tq = 0; tq < TQ_; tq++) {
        float sc[9];
        float mx = -1e30f;
#pragma unroll
        for (int tk = 0; tk < TQ_; tk++) {
            float p = qv[tq] * kv[tk];
#pragma unroll
            for (int o = 16; o; o >>= 1) p += __shfl_xor_sync(0xffffffffu, p, o);
            float s = p * scale;
            if (mask[tq * TQ_ + tk]) s = -1e9f;
            sc[tk] = s;
            mx = fmaxf(mx, s);
        }
        float denom = 0.f;
#pragma unroll
        for (int tk = 0; tk < TQ_; tk++) { sc[tk] = expf(sc[tk] - mx); denom += sc[tk]; }
        float invd = 1.f / denom;
        float o_acc = 0.f;
#pragma unroll
        for (int tk = 0; tk < TQ_; tk++) o_acc = fmaf(sc[tk] * invd, vv[tk], o_acc);
        O[obase + tq * ostride] = __float2bfloat16(o_acc);
    }
}

// ---------------------------------------------------------------------------
// CLS frame averaging
// ---------------------------------------------------------------------------
__global__ void cls_avg_kernel(float* __restrict__ y)
{
    int b = blockIdx.x;
    int d = threadIdx.x;
    size_t base = (size_t)b * TQ_ * HW_ * D_MODEL;
    float s = 0.f;
    for (int hw = 0; hw < HW_; hw++) s += y[base + (size_t)hw * D_MODEL + d];
    float avg = s * (1.f / HW_);
    for (int hw = 0; hw < HW_; hw++) y[base + (size_t)hw * D_MODEL + d] = avg;
}

// ---------------------------------------------------------------------------

template <typename OutT, bool GELU, bool RES>
static inline void run_gemm(const __nv_bfloat16* A, const __nv_bfloat16* W,
                            const float* bias, const float* res, OutT* C,
                            int M, int N, int K)
{
    dim3 grid(N / BN, M / BM);
    gemm_bf16_kernel<OutT, GELU, RES><<<grid, 256>>>(A, W, bias, res, C, M, N, K);
}

extern "C" void kernel_launch(void* const* d_in, const int* in_sizes, int n_in,
                              void* d_out, int out_size)
{
    const float* query = (const float*)d_in[0];
    const unsigned char* tmask = (const unsigned char*)d_in[2];
    const float* sln_g = (const float*)d_in[3];
    const float* sln_b = (const float*)d_in[4];
    const float* s_wq = (const float*)d_in[5];
    const float* s_bq = (const float*)d_in[6];
    const float* s_wk = (const float*)d_in[7];
    const float* s_bk = (const float*)d_in[8];
    const float* s_wv = (const float*)d_in[9];
    const float* s_bv = (const float*)d_in[10];
    const float* s_wo = (const float*)d_in[11];
    const float* s_bo = (const float*)d_in[12];
    const float* tln_g = (const float*)d_in[13];
    const float* tln_b = (const float*)d_in[14];
    const float* t_wq = (const float*)d_in[15];
    const float* t_bq = (const float*)d_in[16];
    const float* t_wk = (const float*)d_in[17];
    const float* t_bk = (const float*)d_in[18];
    const float* t_wv = (const float*)d_in[19];
    const float* t_bv = (const float*)d_in[20];
    const float* t_wo = (const float*)d_in[21];
    const float* t_bo = (const float*)d_in[22];
    const float* mln_g = (const float*)d_in[23];
    const float* mln_b = (const float*)d_in[24];
    const float* w1 = (const float*)d_in[25];
    const float* b1 = (const float*)d_in[26];
    const float* w2 = (const float*)d_in[27];
    const float* b2 = (const float*)d_in[28];
    float* out = (float*)d_out;

    __nv_bfloat16 *lnb, *aob, *hidb, *wsp, *wtp, *wso, *wto, *wb1, *wb2;
    float *qkv, *x, *y, *tmp, *bsp, *btp;
    cudaGetSymbolAddress((void**)&lnb,  g_lnb);
    cudaGetSymbolAddress((void**)&qkv,  g_qkv);
    cudaGetSymbolAddress((void**)&aob,  g_aob);
    cudaGetSymbolAddress((void**)&x,    g_x);
    cudaGetSymbolAddress((void**)&y,    g_y);
    cudaGetSymbolAddress((void**)&tmp,  g_tmp);
    cudaGetSymbolAddress((void**)&hidb, g_hidb);
    cudaGetSymbolAddress((void**)&wsp,  g_wsp);
    cudaGetSymbolAddress((void**)&wtp,  g_wtp);
    cudaGetSymbolAddress((void**)&wso,  g_wso);
    cudaGetSymbolAddress((void**)&wto,  g_wto);
    cudaGetSymbolAddress((void**)&wb1,  g_w1);
    cudaGetSymbolAddress((void**)&wb2,  g_w2);
    cudaGetSymbolAddress((void**)&bsp,  g_bsp);
    cudaGetSymbolAddress((void**)&btp,  g_btp);

    // ---- Prologue: convert/pack weights to bf16 ----
    const int WN = D_MODEL * D_MODEL;          // 65536
    const int WM = D_MODEL * MLP_;             // 262144
    cvt_pack_kernel<<<WN / 256, 256>>>(s_wq, wsp, WN, D_MODEL, 768, 0);
    cvt_pack_kernel<<<WN / 256, 256>>>(s_wk, wsp, WN, D_MODEL, 768, 256);
    cvt_pack_kernel<<<WN / 256, 256>>>(s_wv, wsp, WN, D_MODEL, 768, 512);
    cvt_pack_kernel<<<WN / 256, 256>>>(t_wq, wtp, WN, D_MODEL, 768, 0);
    cvt_pack_kernel<<<WN / 256, 256>>>(t_wk, wtp, WN, D_MODEL, 768, 256);
    cvt_pack_kernel<<<WN / 256, 256>>>(t_wv, wtp, WN, D_MODEL, 768, 512);
    cvt_pack_kernel<<<WN / 256, 256>>>(s_wo, wso, WN, D_MODEL, D_MODEL, 0);
    cvt_pack_kernel<<<WN / 256, 256>>>(t_wo, wto, WN, D_MODEL, D_MODEL, 0);
    cvt_pack_kernel<<<WM / 256, 256>>>(w1, wb1, WM, MLP_, MLP_, 0);
    cvt_pack_kernel<<<WM / 256, 256>>>(w2, wb2, WM, D_MODEL, D_MODEL, 0);
    pack_bias_kernel<<<1, 256>>>(s_bq, bsp, 256, 0);
    pack_bias_kernel<<<1, 256>>>(s_bk, bsp, 256, 256);
    pack_bias_kernel<<<1, 256>>>(s_bv, bsp, 256, 512);
    pack_bias_kernel<<<1, 256>>>(t_bq, btp, 256, 0);
    pack_bias_kernel<<<1, 256>>>(t_bk, btp, 256, 256);
    pack_bias_kernel<<<1, 256>>>(t_bv, btp, 256, 512);

    // ---- Stage A: spatial windowed attention (frames 0..7) ----
    ln_kernel<<<MS / 8, 256>>>(query, lnb, sln_g, sln_b, MS, TQ_ * HW_, TS_ * HW_);
    run_gemm<float, false, false>(lnb, wsp, bsp, nullptr, qkv, MS, 768, D_MODEL);
    spatial_attn_kernel<<<MS, 256>>>(qkv, aob);
    run_gemm<float, false, false>(aob, wso, s_bo, nullptr, tmp, MS, D_MODEL, D_MODEL);
    assemble_x_kernel<<<MT * D_MODEL / 256, 256>>>(query, tmp, x);

    // ---- Stage B: temporal RoPE attention ----
    ln_kernel<<<MT / 8, 256>>>(x, lnb, tln_g, tln_b, MT, TQ_ * HW_, TQ_ * HW_);
    run_gemm<float, false, false>(lnb, wtp, btp, nullptr, qkv, MT, 768, D_MODEL);
    temporal_attn_kernel<<<B_ * HW_, 256>>>(qkv, tmask, aob);
    run_gemm<float, false, true>(aob, wto, t_bo, x, y, MT, D_MODEL, D_MODEL);

    // CLS frame averaging (in place on y)
    cls_avg_kernel<<<B_, D_MODEL>>>(y);

    // ---- Stage C: MLP ----
    ln_kernel<<<MT / 8, 256>>>(y, lnb, mln_g, mln_b, MT, TQ_ * HW_, TQ_ * HW_);
    run_gemm<__nv_bfloat16, true, false>(lnb, wb1, b1, nullptr, hidb, MT, MLP_, D_MODEL);
    run_gemm<float, false, true>(hidb, wb2, b2, y, out, MT, D_MODEL, MLP_);
}